// round 16
// baseline (speedup 1.0000x reference)
#include <cuda_runtime.h>
#include <cuda_fp16.h>
#include <cuda_bf16.h>
#include <cstdint>

// Problem constants
#define NTOK   4096      // 64*64 tokens
#define DIM    768
#define NH     12
#define HD     64
#define GRID_HW 64
#define QKSCALE 0.125f   // 64^-0.5
#define LOG2E   1.44269504f
#define M0SHIFT 5.77078016f   // 4.0 * log2(e)
#define NSPLIT 3              // split-KV factor

// ---------------- scratch (device globals; no allocation allowed) ----------
__device__ __align__(16) __half g_qh[NH * NTOK * HD];  // fp16 q PRE-SCALED by 0.125*log2e
__device__ __align__(16) __half g_k[NH * NTOK * HD];   // fp16 k, [head][tok][d]
__device__ __align__(16) __half g_v[NH * HD * NTOK];   // fp16 v TRANSPOSED [head][d][tok]
__device__ float g_relh[NH * NTOK * HD];               // [head][n][kh], LOG2 DOMAIN
__device__ float g_relw[NH * NTOK * HD];               // [head][n][kw], LOG2 DOMAIN
__device__ float g_po[NSPLIT * NH * NTOK * HD];        // split-KV unnormalized O
__device__ float g_pl[NSPLIT * NH * NTOK];             // split-KV partial l
// fp16 GEMM operands
__device__ __align__(16) __half g_xh[NTOK * DIM];      // x fp16
__device__ __align__(16) __half g_wqh[DIM * 3 * DIM];  // w_qkv fp16
__device__ __align__(16) __half g_wph[DIM * DIM];      // w_proj fp16
__device__ __align__(16) __half g_aoh[NTOK * DIM];     // attention out fp16
__device__ __align__(16) __half g_rph[127 * HD];       // rel_pos_h fp16
__device__ __align__(16) __half g_rpw[127 * HD];       // rel_pos_w fp16

// ---------------------------------------------------------------------------
// helpers
// ---------------------------------------------------------------------------
__device__ __forceinline__ __half2 ex2h2(__half2 x) {
    __half2 y;
    asm("ex2.approx.f16x2 %0, %1;"
        : "=r"(*reinterpret_cast<unsigned*>(&y))
        : "r"(*reinterpret_cast<unsigned*>(&x)));
    return y;
}

__device__ __forceinline__ void mma_f16(float c[4],
                                        unsigned a0, unsigned a1, unsigned a2, unsigned a3,
                                        unsigned b0, unsigned b1) {
    asm volatile(
        "mma.sync.aligned.m16n8k16.row.col.f32.f16.f16.f32 "
        "{%0,%1,%2,%3}, {%4,%5,%6,%7}, {%8,%9}, {%0,%1,%2,%3};\n"
        : "+f"(c[0]), "+f"(c[1]), "+f"(c[2]), "+f"(c[3])
        : "r"(a0), "r"(a1), "r"(a2), "r"(a3), "r"(b0), "r"(b1));
}

__device__ __forceinline__ void ldsm4(unsigned* d, uint32_t addr) {
    asm volatile("ldmatrix.sync.aligned.m8n8.x4.shared.b16 {%0,%1,%2,%3}, [%4];\n"
                 : "=r"(d[0]), "=r"(d[1]), "=r"(d[2]), "=r"(d[3]) : "r"(addr));
}

__device__ __forceinline__ void ldsm4t(unsigned* d, uint32_t addr) {
    asm volatile("ldmatrix.sync.aligned.m8n8.x4.trans.shared.b16 {%0,%1,%2,%3}, [%4];\n"
                 : "=r"(d[0]), "=r"(d[1]), "=r"(d[2]), "=r"(d[3]) : "r"(addr));
}

__device__ __forceinline__ void cp16(uint32_t dst, const void* src) {
    asm volatile("cp.async.cg.shared.global [%0], [%1], 16;\n" :: "r"(dst), "l"(src));
}
#define CP_COMMIT() asm volatile("cp.async.commit_group;\n")

// ---------------------------------------------------------------------------
// fused conversion kernel (fp32 -> fp16)
// ---------------------------------------------------------------------------
#define NX4  (NTOK * DIM / 4)
#define NWQ4 (DIM * 3 * DIM / 4)
#define NWP4 (DIM * DIM / 4)
#define NRP4 (127 * HD / 4)

__global__ void conv_all_kernel(const float* __restrict__ x,
                                const float* __restrict__ wq,
                                const float* __restrict__ wp,
                                const float* __restrict__ rh,
                                const float* __restrict__ rw)
{
    int i = blockIdx.x * 256 + threadIdx.x;
    const float* src;
    __half* dst;
    int off;
    if (i < NX4)                          { src = x;  dst = g_xh;  off = i; }
    else if ((i -= NX4) < NWQ4)           { src = wq; dst = g_wqh; off = i; }
    else if ((i -= NWQ4) < NWP4)          { src = wp; dst = g_wph; off = i; }
    else if ((i -= NWP4) < NRP4)          { src = rh; dst = g_rph; off = i; }
    else if ((i -= NRP4) < NRP4)          { src = rw; dst = g_rpw; off = i; }
    else return;
    float4 v = ((const float4*)src)[off];
    __half2 h0 = __floats2half2_rn(v.x, v.y);
    __half2 h1 = __floats2half2_rn(v.z, v.w);
    ((uint2*)dst)[off] = make_uint2(*(unsigned*)&h0, *(unsigned*)&h1);
}

// ---------------------------------------------------------------------------
// fp16 x1 GEMM, 4-stage cp.async pipeline (round-15 version, unchanged)
// ---------------------------------------------------------------------------
#define AST_B 48
#define BST_B 272
#define A_STG_B (128 * AST_B)
#define B_STG_B (16 * BST_B)
#define GEMM_SMEM_B (4 * (A_STG_B + B_STG_B))  // 41984

__global__ void __launch_bounds__(256)
gemm_f16_kernel(const __half* __restrict__ Ah_g,
                const __half* __restrict__ Bh_g,
                const float* __restrict__ bias,
                float* __restrict__ C,
                int N, int K, int qkv_mode)
{
    extern __shared__ char gsmc[];
    char* Asm = gsmc;
    char* Bsm = gsmc + 4 * A_STG_B;

    const int bx = blockIdx.x, by = blockIdx.y;
    const int t  = threadIdx.x;
    const int lane = t & 31, w = t >> 5;
    const int r = lane >> 2, c = lane & 3;
    const int wm = w >> 1, wn = w & 1;
    const int m0 = by * 128, n0 = bx * 128;
    const int mw = wm * 32,  nw = wn * 64;

    const int aRow  = lane & 15;
    const int aColB = (lane >> 4) * 16;
    const int bRow  = (lane & 7) + ((lane >> 3) & 1) * 8;
    const int bColB = ((lane >> 4) & 1) * 16;

    const int arow = t >> 1;
    const int acol = (t & 1) * 16;
    const int brow = t >> 4;
    const int bcol = (t & 15) * 16;

    const char* Ag = (const char*)(Ah_g + (int64_t)(m0 + arow) * K) + acol;
    const char* Bg = (const char*)(Bh_g + n0) + bcol;

    const uint32_t as_b = (uint32_t)__cvta_generic_to_shared(Asm);
    const uint32_t bs_b = (uint32_t)__cvta_generic_to_shared(Bsm);
    const uint32_t a_dst = as_b + (uint32_t)(arow * AST_B + acol);
    const uint32_t b_dst = bs_b + (uint32_t)(brow * BST_B + bcol);

    float acc[2][8][4];
#pragma unroll
    for (int mg = 0; mg < 2; mg++)
#pragma unroll
        for (int ng = 0; ng < 8; ng++)
#pragma unroll
            for (int j = 0; j < 4; j++) acc[mg][ng][j] = 0.f;

    const int nk = K / 16;

    #define G_LDG(st, i) do {                                               \
        const int kg_ = (i) * 16;                                           \
        cp16(a_dst + (uint32_t)((st) * A_STG_B), Ag + kg_ * 2);             \
        cp16(b_dst + (uint32_t)((st) * B_STG_B),                            \
             Bg + (int64_t)(kg_ + brow) * N * 2);                           \
    } while (0)

    G_LDG(0, 0); CP_COMMIT();
    G_LDG(1, 1); CP_COMMIT();

    for (int i = 0; i < nk; i++) {
        const int s = i & 3;
        if (!(i & 1)) {
            asm volatile("cp.async.wait_group 0;\n");
            __syncthreads();
            if (i + 2 < nk) G_LDG((i + 2) & 3, i + 2);
            CP_COMMIT();
            if (i + 3 < nk) G_LDG((i + 3) & 3, i + 3);
            CP_COMMIT();
        }

        const uint32_t aB  = as_b + (uint32_t)(s * A_STG_B + (mw + aRow) * AST_B + aColB);
        const uint32_t bhB = bs_b + (uint32_t)(s * B_STG_B + bRow * BST_B + bColB);

        unsigned ah[2][4];
#pragma unroll
        for (int mg = 0; mg < 2; mg++)
            ldsm4(ah[mg], aB + (uint32_t)(mg * 16 * AST_B));
#pragma unroll
        for (int g = 0; g < 4; g++) {
            unsigned bh[4];
            ldsm4t(bh, bhB + (uint32_t)((nw + g * 16) * 2));
#pragma unroll
            for (int half = 0; half < 2; half++) {
                const unsigned b0 = bh[half * 2], b1 = bh[half * 2 + 1];
                const int ng = g * 2 + half;
#pragma unroll
                for (int mg = 0; mg < 2; mg++)
                    mma_f16(acc[mg][ng], ah[mg][0], ah[mg][1], ah[mg][2], ah[mg][3], b0, b1);
            }
        }
    }

    const float qsc = QKSCALE * LOG2E;
#pragma unroll
    for (int mg = 0; mg < 2; mg++) {
        const int row0 = m0 + mw + mg * 16 + r;
        const int row1 = row0 + 8;
#pragma unroll
        for (int ng = 0; ng < 8; ng++) {
            const int col = n0 + nw + ng * 8 + 2 * c;
            const float bs0 = bias[col], bs1 = bias[col + 1];
            float v00 = acc[mg][ng][0] + bs0, v01 = acc[mg][ng][1] + bs1;
            float v10 = acc[mg][ng][2] + bs0, v11 = acc[mg][ng][3] + bs1;
            if (qkv_mode == 0) {
                *(float2*)&C[(int64_t)row0 * N + col] = make_float2(v00, v01);
                *(float2*)&C[(int64_t)row1 * N + col] = make_float2(v10, v11);
            } else {
                const int part = col / DIM;
                const int rest = col - part * DIM;
                const int head = rest >> 6;
                const int d0   = rest & 63;
                if (part == 0) {
                    *(__half2*)&g_qh[(head * NTOK + row0) * HD + d0] =
                        __floats2half2_rn(v00 * qsc, v01 * qsc);
                    *(__half2*)&g_qh[(head * NTOK + row1) * HD + d0] =
                        __floats2half2_rn(v10 * qsc, v11 * qsc);
                } else if (part == 1) {
                    *(__half2*)&g_k[(head * NTOK + row0) * HD + d0] = __floats2half2_rn(v00, v01);
                    *(__half2*)&g_k[(head * NTOK + row1) * HD + d0] = __floats2half2_rn(v10, v11);
                } else {
                    __half* vt = g_v + head * HD * NTOK;
                    vt[(d0    ) * NTOK + row0] = __float2half_rn(v00);
                    vt[(d0 + 1) * NTOK + row0] = __float2half_rn(v01);
                    vt[(d0    ) * NTOK + row1] = __float2half_rn(v10);
                    vt[(d0 + 1) * NTOK + row1] = __float2half_rn(v11);
                }
            }
        }
    }
}

// ---------------------------------------------------------------------------
// Tensor-core rel-pos (unchanged from round 13)
// ---------------------------------------------------------------------------
__global__ void __launch_bounds__(128)
relpos_tc_kernel(const __half* __restrict__ gqh,
                 const __half* __restrict__ rph,
                 const __half* __restrict__ rpw,
                 float* __restrict__ outh,
                 float* __restrict__ outw)
{
    __shared__ __align__(16) char Asm[64 * 144];
    __shared__ __align__(16) char Bsm[64 * 144];

    const int fixed = blockIdx.x;
    const int head  = blockIdx.y;
    const int mode  = blockIdx.z;
    const int t     = threadIdx.x;
    const int lane  = t & 31;
    const int w     = t >> 5;
    const int r     = lane >> 2;
    const int c     = lane & 3;

    const __half* rp = mode ? rpw : rph;
    float* out = mode ? outw : outh;
    const __half* qbase = gqh + head * NTOK * HD;

    const uint32_t as_sm = (uint32_t)__cvta_generic_to_shared(Asm);
    const uint32_t bs_sm = (uint32_t)__cvta_generic_to_shared(Bsm);

#pragma unroll
    for (int i = 0; i < 4; i++) {
        const int ch = t + i * 128;
        const int row = ch >> 3, co = (ch & 7) * 16;
        const int tok = mode ? (row * 64 + fixed) : (fixed * 64 + row);
        cp16(as_sm + (uint32_t)(row * 144 + co), (const char*)(qbase + tok * HD) + co);
        cp16(bs_sm + (uint32_t)(row * 144 + co), (const char*)(rp + (fixed - row + 63) * HD) + co);
    }
    CP_COMMIT();
    asm volatile("cp.async.wait_group 0;\n");
    __syncthreads();

    const uint32_t aB = as_sm + (uint32_t)((w * 16 + (lane & 15)) * 144 + (lane >> 4) * 16);
    const uint32_t bB = bs_sm + (uint32_t)((lane & 15) * 144 + (lane >> 4) * 16);

    unsigned qa[4][4];
#pragma unroll
    for (int kk = 0; kk < 4; kk++)
        ldsm4(qa[kk], aB + (uint32_t)(kk * 32));

    float S[8][4];
#pragma unroll
    for (int n = 0; n < 8; n++)
#pragma unroll
        for (int j = 0; j < 4; j++) S[n][j] = 0.f;

#pragma unroll
    for (int kk = 0; kk < 4; kk++) {
#pragma unroll
        for (int g = 0; g < 4; g++) {
            unsigned bb[4];
            ldsm4(bb, bB + (uint32_t)(g * 16 * 144 + kk * 32));
            mma_f16(S[g*2],   qa[kk][0], qa[kk][1], qa[kk][2], qa[kk][3], bb[0], bb[2]);
            mma_f16(S[g*2+1], qa[kk][0], qa[kk][1], qa[kk][2], qa[kk][3], bb[1], bb[3]);
        }
    }

    const int arow0 = w * 16 + r, arow1 = arow0 + 8;
    const int tok0 = mode ? (arow0 * 64 + fixed) : (fixed * 64 + arow0);
    const int tok1 = mode ? (arow1 * 64 + fixed) : (fixed * 64 + arow1);
    float* o0 = out + (head * NTOK + tok0) * HD;
    float* o1 = out + (head * NTOK + tok1) * HD;
#pragma unroll
    for (int n = 0; n < 8; n++) {
        const int col = n * 8 + 2 * c;
        *(float2*)&o0[col] = make_float2(S[n][0] * 8.f, S[n][1] * 8.f);
        *(float2*)&o1[col] = make_float2(S[n][2] * 8.f, S[n][3] * 8.f);
    }
}

// ---------------------------------------------------------------------------
// Flash attention v16: 256 threads = 8 warps x 16 Q-rows (2 CTAs/SM = 16
// warps/SM), 3-stage cp.async K/V pipeline, f16x2 softmax, l via ones-MMA,
// split-KV x3 (22/21/21).
// ---------------------------------------------------------------------------
#define STRH      72
#define ROW_B     144
#define KV_TILE_B (64 * ROW_B)               // 9216 B per tile
#define PQ_B      (128 * ROW_B)              // 18432 B
#define FLASH_SMEM_B (6 * KV_TILE_B + PQ_B)  // 73728 B
#define ONESH2 0x3C003C00u

__global__ void __launch_bounds__(256, 2)
flash_v16_kernel(const __half* __restrict__ gqh,
                 const __half* __restrict__ gk,
                 const __half* __restrict__ gvt,
                 const float* __restrict__ grh,
                 const float* __restrict__ grw,
                 float* __restrict__ po,
                 float* __restrict__ pl)
{
    extern __shared__ char smc[];
    char*   Ksc = smc;                        // 3 stages x 64 x 144B
    char*   Vsc = smc + 3 * KV_TILE_B;        // 3 stages x 64 x 144B
    __half* PQh = (__half*)(smc + 6 * KV_TILE_B);   // 128 x 72 halves (Q -> P)

    const int qt   = blockIdx.x;
    const int head = blockIdx.y;
    const int z    = blockIdx.z;
    const int ktb  = (z == 0) ? 0 : (22 + 21 * (z - 1));   // 0, 22, 43
    const int nit  = (z == 0) ? 22 : 21;
    const int t    = threadIdx.x;    // 256
    const int lane = t & 31;
    const int w    = t >> 5;         // 0..7
    const int r    = lane >> 2;
    const int c    = lane & 3;
    const int mbase = w * 16;        // warp owns 16 Q rows

    const __half* qbh  = gqh + (head * NTOK + qt * 128) * HD;
    const __half* kb0  = gk  + head * NTOK * HD;
    const char*   vtb0 = (const char*)(gvt + head * HD * NTOK);
    const float*  rhb  = grh + (head * NTOK + qt * 128 + mbase) * HD;
    const float*  rwb  = grw + (head * NTOK + qt * 128 + mbase) * HD;

    const uint32_t ks_sm = (uint32_t)__cvta_generic_to_shared(Ksc);
    const uint32_t vs_sm = (uint32_t)__cvta_generic_to_shared(Vsc);
    const uint32_t pq_sm = (uint32_t)__cvta_generic_to_shared(PQh);

    // K/V tile loader: 512 chunks of 16B per operand, 2 per thread
    #define LOAD_KV(st, kt) do {                                              \
        const char* kb_ = (const char*)(kb0 + (kt) * 64 * HD);                \
        const uint32_t kd_ = ks_sm + (uint32_t)((st) * KV_TILE_B);            \
        const uint32_t vd_ = vs_sm + (uint32_t)((st) * KV_TILE_B);            \
        _Pragma("unroll")                                                     \
        for (int i_ = 0; i_ < 2; i_++) {                                      \
            const int ch_ = t + i_ * 256;                                     \
            const int row_ = ch_ >> 3, co_ = (ch_ & 7) * 16;                  \
            cp16(kd_ + row_ * ROW_B + co_, kb_ + row_ * 128 + co_);           \
            cp16(vd_ + row_ * ROW_B + co_,                                    \
                 vtb0 + row_ * (NTOK * 2) + (kt) * 128 + co_);                \
        }                                                                     \
    } while (0)

    // prologue: prefetch K/V tiles ktb, ktb+1 and Q
    LOAD_KV(0, ktb);     CP_COMMIT();
    LOAD_KV(1, ktb + 1); CP_COMMIT();
#pragma unroll
    for (int i_ = 0; i_ < 4; i_++) {
        const int ch_ = t + i_ * 256;
        const int row_ = ch_ >> 3, co_ = (ch_ & 7) * 16;
        cp16(pq_sm + (uint32_t)(row_ * ROW_B + co_), (const char*)qbh + row_ * 128 + co_);
    }
    CP_COMMIT();
    asm volatile("cp.async.wait_group 0;\n");
    __syncthreads();

    // Q fragments (persist): 16 rows -> qa[kk][4]
    const uint32_t aBase = pq_sm + (uint32_t)((mbase + (lane & 15)) * ROW_B
                                              + (lane >> 4) * 16);
    unsigned qa[4][4];
#pragma unroll
    for (int kk = 0; kk < 4; kk++)
        ldsm4(qa[kk], aBase + (uint32_t)(kk * 32));
    __syncwarp();

    // rw bias (log2 domain), packed fp16x2: [rowgroup][n]
    __half2 rwh[2][8];
#pragma unroll
    for (int rg = 0; rg < 2; rg++)
#pragma unroll
        for (int n = 0; n < 8; n++) {
            float2 v = *(const float2*)&rwb[(rg * 8 + r) * HD + n * 8 + 2 * c];
            rwh[rg][n] = __floats2half2_rn(v.x, v.y);
        }

    float O[8][4];
#pragma unroll
    for (int n = 0; n < 8; n++)
#pragma unroll
        for (int j = 0; j < 4; j++) O[n][j] = 0.f;
    float lacc[4] = {0.f, 0.f, 0.f, 0.f};

    for (int it = 0; it < nit; it++) {
        const int kt = ktb + it;
        const int s  = it % 3;

        asm volatile("cp.async.wait_group 1;\n");
        __syncthreads();   // tile kt ready; stage (it+2)%3 free

        if (it + 2 < nit) LOAD_KV((it + 2) % 3, kt + 2);
        CP_COMMIT();

        const float rh0 = __ldg(&rhb[r * HD + kt])       - M0SHIFT;
        const float rh1 = __ldg(&rhb[(8 + r) * HD + kt]) - M0SHIFT;

        const uint32_t kS = ks_sm + (uint32_t)(s * KV_TILE_B)
                              + (lane & 15) * ROW_B + (lane >> 4) * 16;
        const uint32_t vS = vs_sm + (uint32_t)(s * KV_TILE_B)
                              + (lane & 15) * ROW_B + (lane >> 4) * 16;

        // ---- S = Q K^T over full 64 keys ----
        float S[8][4];
#pragma unroll
        for (int n = 0; n < 8; n++)
#pragma unroll
            for (int j = 0; j < 4; j++) S[n][j] = 0.f;

#pragma unroll
        for (int kk = 0; kk < 4; kk++) {
#pragma unroll
            for (int g = 0; g < 4; g++) {
                unsigned bb[4];
                ldsm4(bb, kS + (uint32_t)(g * 16 * ROW_B + kk * 32));
                mma_f16(S[g*2],   qa[kk][0], qa[kk][1], qa[kk][2], qa[kk][3], bb[0], bb[2]);
                mma_f16(S[g*2+1], qa[kk][0], qa[kk][1], qa[kk][2], qa[kk][3], bb[1], bb[3]);
            }
        }

        // ---- fixed-shift softmax: p = 2^(S + rh' + rw'), f16x2 exp ----
        {
            __half* prow0 = PQh + (mbase + r) * STRH + 2 * c;
            __half* prow1 = prow0 + 8 * STRH;
#pragma unroll
            for (int n = 0; n < 8; n++) {
                __half2 h01 = __floats2half2_rn(S[n][0] + rh0, S[n][1] + rh0);
                __half2 h23 = __floats2half2_rn(S[n][2] + rh1, S[n][3] + rh1);
                __half2 p01 = ex2h2(__hadd2(h01, rwh[0][n]));
                __half2 p23 = ex2h2(__hadd2(h23, rwh[1][n]));
                *(__half2*)(prow0 + n * 8) = p01;
                *(__half2*)(prow1 + n * 8) = p23;
            }
        }
        __syncwarp();   // P rows warp-private

        // ---- O += P V; l += P * ones ----
#pragma unroll
        for (int kk2 = 0; kk2 < 4; kk2++) {
            unsigned pa[4];
            ldsm4(pa, aBase + (uint32_t)(kk2 * 32));
            mma_f16(lacc, pa[0], pa[1], pa[2], pa[3], ONESH2, ONESH2);
#pragma unroll
            for (int p = 0; p < 4; p++) {
                unsigned vv[4];
                ldsm4(vv, vS + (uint32_t)(p * 16 * ROW_B + kk2 * 32));
                mma_f16(O[p*2],   pa[0], pa[1], pa[2], pa[3], vv[0], vv[2]);
                mma_f16(O[p*2+1], pa[0], pa[1], pa[2], pa[3], vv[1], vv[3]);
            }
        }
        __syncwarp();   // P reads done before next iter's stores
    }

    // ---- epilogue ----
    const int pz = z * NH * NTOK + head * NTOK;
    const int row0 = qt * 128 + mbase + r;
    const int row1 = row0 + 8;
    if (c == 0) {
        pl[pz + row0] = lacc[0];
        pl[pz + row1] = lacc[2];
    }
#pragma unroll
    for (int n = 0; n < 8; n++) {
        const int col = n * 8 + 2 * c;
        *(float2*)&po[(pz + row0) * HD + col] = make_float2(O[n][0], O[n][1]);
        *(float2*)&po[(pz + row1) * HD + col] = make_float2(O[n][2], O[n][3]);
    }
}

// ---------------------------------------------------------------------------
// merge the three KV-third partials -> g_aoh (fp16, feeds proj GEMM)
// ---------------------------------------------------------------------------
__global__ void merge_kernel(const float* __restrict__ po,
                             const float* __restrict__ pl,
                             __half* __restrict__ aoh)
{
    const int gid = blockIdx.x * 256 + threadIdx.x;
    const int dp  = (gid & 7) * 8;
    const int hr  = gid >> 3;
    const int head = hr >> 12, row = hr & 4095;
    const int S = NH * NTOK;

    const float inv = 1.0f / (pl[hr] + pl[S + hr] + pl[2 * S + hr]);

    const float* o0 = po + (size_t)hr * HD + dp;
    const float* o1 = po + (size_t)(S + hr) * HD + dp;
    const float* o2 = po + (size_t)(2 * S + hr) * HD + dp;
    __half* dst = aoh + row * DIM + head * HD + dp;

    uint4 outw;
    unsigned* ow = (unsigned*)&outw;
#pragma unroll
    for (int j = 0; j < 8; j += 2) {
        float x = (o0[j]     + o1[j]     + o2[j])     * inv;
        float y = (o0[j + 1] + o1[j + 1] + o2[j + 1]) * inv;
        __half2 h = __floats2half2_rn(x, y);
        ow[j >> 1] = *(unsigned*)&h;
    }
    *(uint4*)dst = outw;
}

// ---------------------------------------------------------------------------
extern "C" void kernel_launch(void* const* d_in, const int* in_sizes, int n_in,
                              void* d_out, int out_size)
{
    const float* x        = (const float*)d_in[0];
    const float* w_qkv    = (const float*)d_in[1];
    const float* b_qkv    = (const float*)d_in[2];
    const float* w_proj   = (const float*)d_in[3];
    const float* b_proj   = (const float*)d_in[4];
    const float* rel_h    = (const float*)d_in[5];
    const float* rel_w    = (const float*)d_in[6];
    float* out = (float*)d_out;

    float *grh, *grw, *gpo, *gpl;
    __half *gqh, *gk, *gv, *gxh, *gwqh, *gwph, *gaoh, *grph, *grpw;
    cudaGetSymbolAddress((void**)&gqh,  g_qh);
    cudaGetSymbolAddress((void**)&gk,   g_k);
    cudaGetSymbolAddress((void**)&gv,   g_v);
    cudaGetSymbolAddress((void**)&grh,  g_relh);
    cudaGetSymbolAddress((void**)&grw,  g_relw);
    cudaGetSymbolAddress((void**)&gpo,  g_po);
    cudaGetSymbolAddress((void**)&gpl,  g_pl);
    cudaGetSymbolAddress((void**)&gxh,  g_xh);
    cudaGetSymbolAddress((void**)&gwqh, g_wqh);
    cudaGetSymbolAddress((void**)&gwph, g_wph);
    cudaGetSymbolAddress((void**)&gaoh, g_aoh);
    cudaGetSymbolAddress((void**)&grph, g_rph);
    cudaGetSymbolAddress((void**)&grpw, g_rpw);

    // 0) fused conversion of all operands to fp16
    const int NCONV = NX4 + NWQ4 + NWP4 + 2 * NRP4;
    conv_all_kernel<<<(NCONV + 255) / 256, 256>>>(x, w_qkv, w_proj, rel_h, rel_w);

    cudaFuncSetAttribute(gemm_f16_kernel,
                         cudaFuncAttributeMaxDynamicSharedMemorySize, GEMM_SMEM_B);

    // 1) QKV GEMM (fp16 x1, 4-stage cp.async)
    gemm_f16_kernel<<<dim3(3 * DIM / 128, NTOK / 128), 256, GEMM_SMEM_B>>>(
        gxh, gwqh, b_qkv, nullptr, 3 * DIM, DIM, 1);

    // 2) rel_h / rel_w via tensor cores
    relpos_tc_kernel<<<dim3(GRID_HW, NH, 2), 128>>>(gqh, grph, grpw, grh, grw);

    // 3) flash attention v16 (256 thr, 8 warps x 16 rows, 3-stage, split x3)
    cudaFuncSetAttribute(flash_v16_kernel,
                         cudaFuncAttributeMaxDynamicSharedMemorySize, FLASH_SMEM_B);
    flash_v16_kernel<<<dim3(NTOK / 128, NH, NSPLIT), 256, FLASH_SMEM_B>>>(
        gqh, gk, gv, grh, grw, gpo, gpl);

    // 4) merge partials -> fp16 ao
    merge_kernel<<<NH * NTOK * 8 / 256, 256>>>(gpo, gpl, gaoh);

    // 5) output projection (fp16 x1, 4-stage cp.async)
    gemm_f16_kernel<<<dim3(DIM / 128, NTOK / 128), 256, GEMM_SMEM_B>>>(
        gaoh, gwph, b_proj, out, DIM, DIM, 0);
}

// round 17
// speedup vs baseline: 1.0452x; 1.0452x over previous
#include <cuda_runtime.h>
#include <cuda_fp16.h>
#include <cuda_bf16.h>
#include <cstdint>

// Problem constants
#define NTOK   4096      // 64*64 tokens
#define DIM    768
#define NH     12
#define HD     64
#define GRID_HW 64
#define QKSCALE 0.125f   // 64^-0.5
#define LOG2E   1.44269504f
#define M0SHIFT 5.77078016f   // 4.0 * log2(e)
#define NSPLIT 3              // split-KV factor

// ---------------- scratch (device globals; no allocation allowed) ----------
__device__ __align__(16) __half g_qh[NH * NTOK * HD];  // fp16 q PRE-SCALED by 0.125*log2e
__device__ __align__(16) __half g_k[NH * NTOK * HD];   // fp16 k, [head][tok][d]
__device__ __align__(16) __half g_v[NH * HD * NTOK];   // fp16 v TRANSPOSED [head][d][tok]
__device__ float g_relh[NH * NTOK * HD];               // [head][n][kh], LOG2 DOMAIN
__device__ float g_relw[NH * NTOK * HD];               // [head][n][kw], LOG2 DOMAIN
__device__ float g_po[NSPLIT * NH * NTOK * HD];        // split-KV unnormalized O
__device__ float g_pl[NSPLIT * NH * NTOK];             // split-KV partial l
// fp16 GEMM operands
__device__ __align__(16) __half g_xh[NTOK * DIM];      // x fp16
__device__ __align__(16) __half g_wqh[DIM * 3 * DIM];  // w_qkv fp16
__device__ __align__(16) __half g_wph[DIM * DIM];      // w_proj fp16
__device__ __align__(16) __half g_aoh[NTOK * DIM];     // attention out fp16
__device__ __align__(16) __half g_rph[127 * HD];       // rel_pos_h fp16
__device__ __align__(16) __half g_rpw[127 * HD];       // rel_pos_w fp16

// ---------------------------------------------------------------------------
// helpers
// ---------------------------------------------------------------------------
__device__ __forceinline__ __half2 ex2h2(__half2 x) {
    __half2 y;
    asm("ex2.approx.f16x2 %0, %1;"
        : "=r"(*reinterpret_cast<unsigned*>(&y))
        : "r"(*reinterpret_cast<unsigned*>(&x)));
    return y;
}

__device__ __forceinline__ void mma_f16(float c[4],
                                        unsigned a0, unsigned a1, unsigned a2, unsigned a3,
                                        unsigned b0, unsigned b1) {
    asm volatile(
        "mma.sync.aligned.m16n8k16.row.col.f32.f16.f16.f32 "
        "{%0,%1,%2,%3}, {%4,%5,%6,%7}, {%8,%9}, {%0,%1,%2,%3};\n"
        : "+f"(c[0]), "+f"(c[1]), "+f"(c[2]), "+f"(c[3])
        : "r"(a0), "r"(a1), "r"(a2), "r"(a3), "r"(b0), "r"(b1));
}

__device__ __forceinline__ void ldsm4(unsigned* d, uint32_t addr) {
    asm volatile("ldmatrix.sync.aligned.m8n8.x4.shared.b16 {%0,%1,%2,%3}, [%4];\n"
                 : "=r"(d[0]), "=r"(d[1]), "=r"(d[2]), "=r"(d[3]) : "r"(addr));
}

__device__ __forceinline__ void ldsm4t(unsigned* d, uint32_t addr) {
    asm volatile("ldmatrix.sync.aligned.m8n8.x4.trans.shared.b16 {%0,%1,%2,%3}, [%4];\n"
                 : "=r"(d[0]), "=r"(d[1]), "=r"(d[2]), "=r"(d[3]) : "r"(addr));
}

__device__ __forceinline__ void cp16(uint32_t dst, const void* src) {
    asm volatile("cp.async.cg.shared.global [%0], [%1], 16;\n" :: "r"(dst), "l"(src));
}
#define CP_COMMIT() asm volatile("cp.async.commit_group;\n")

// ---------------------------------------------------------------------------
// fused conversion kernel (fp32 -> fp16)
// ---------------------------------------------------------------------------
#define NX4  (NTOK * DIM / 4)
#define NWQ4 (DIM * 3 * DIM / 4)
#define NWP4 (DIM * DIM / 4)
#define NRP4 (127 * HD / 4)

__global__ void conv_all_kernel(const float* __restrict__ x,
                                const float* __restrict__ wq,
                                const float* __restrict__ wp,
                                const float* __restrict__ rh,
                                const float* __restrict__ rw)
{
    int i = blockIdx.x * 256 + threadIdx.x;
    const float* src;
    __half* dst;
    int off;
    if (i < NX4)                          { src = x;  dst = g_xh;  off = i; }
    else if ((i -= NX4) < NWQ4)           { src = wq; dst = g_wqh; off = i; }
    else if ((i -= NWQ4) < NWP4)          { src = wp; dst = g_wph; off = i; }
    else if ((i -= NWP4) < NRP4)          { src = rh; dst = g_rph; off = i; }
    else if ((i -= NRP4) < NRP4)          { src = rw; dst = g_rpw; off = i; }
    else return;
    float4 v = ((const float4*)src)[off];
    __half2 h0 = __floats2half2_rn(v.x, v.y);
    __half2 h1 = __floats2half2_rn(v.z, v.w);
    ((uint2*)dst)[off] = make_uint2(*(unsigned*)&h0, *(unsigned*)&h1);
}

// ---------------------------------------------------------------------------
// fp16 x1 GEMM, 4-stage cp.async pipeline (round-15 version, measured good)
// ---------------------------------------------------------------------------
#define AST_B 48
#define BST_B 272
#define A_STG_B (128 * AST_B)
#define B_STG_B (16 * BST_B)
#define GEMM_SMEM_B (4 * (A_STG_B + B_STG_B))  // 41984

__global__ void __launch_bounds__(256)
gemm_f16_kernel(const __half* __restrict__ Ah_g,
                const __half* __restrict__ Bh_g,
                const float* __restrict__ bias,
                float* __restrict__ C,
                int N, int K, int qkv_mode)
{
    extern __shared__ char gsmc[];
    char* Asm = gsmc;
    char* Bsm = gsmc + 4 * A_STG_B;

    const int bx = blockIdx.x, by = blockIdx.y;
    const int t  = threadIdx.x;
    const int lane = t & 31, w = t >> 5;
    const int r = lane >> 2, c = lane & 3;
    const int wm = w >> 1, wn = w & 1;
    const int m0 = by * 128, n0 = bx * 128;
    const int mw = wm * 32,  nw = wn * 64;

    const int aRow  = lane & 15;
    const int aColB = (lane >> 4) * 16;
    const int bRow  = (lane & 7) + ((lane >> 3) & 1) * 8;
    const int bColB = ((lane >> 4) & 1) * 16;

    const int arow = t >> 1;
    const int acol = (t & 1) * 16;
    const int brow = t >> 4;
    const int bcol = (t & 15) * 16;

    const char* Ag = (const char*)(Ah_g + (int64_t)(m0 + arow) * K) + acol;
    const char* Bg = (const char*)(Bh_g + n0) + bcol;

    const uint32_t as_b = (uint32_t)__cvta_generic_to_shared(Asm);
    const uint32_t bs_b = (uint32_t)__cvta_generic_to_shared(Bsm);
    const uint32_t a_dst = as_b + (uint32_t)(arow * AST_B + acol);
    const uint32_t b_dst = bs_b + (uint32_t)(brow * BST_B + bcol);

    float acc[2][8][4];
#pragma unroll
    for (int mg = 0; mg < 2; mg++)
#pragma unroll
        for (int ng = 0; ng < 8; ng++)
#pragma unroll
            for (int j = 0; j < 4; j++) acc[mg][ng][j] = 0.f;

    const int nk = K / 16;

    #define G_LDG(st, i) do {                                               \
        const int kg_ = (i) * 16;                                           \
        cp16(a_dst + (uint32_t)((st) * A_STG_B), Ag + kg_ * 2);             \
        cp16(b_dst + (uint32_t)((st) * B_STG_B),                            \
             Bg + (int64_t)(kg_ + brow) * N * 2);                           \
    } while (0)

    G_LDG(0, 0); CP_COMMIT();
    G_LDG(1, 1); CP_COMMIT();

    for (int i = 0; i < nk; i++) {
        const int s = i & 3;
        if (!(i & 1)) {
            asm volatile("cp.async.wait_group 0;\n");
            __syncthreads();
            if (i + 2 < nk) G_LDG((i + 2) & 3, i + 2);
            CP_COMMIT();
            if (i + 3 < nk) G_LDG((i + 3) & 3, i + 3);
            CP_COMMIT();
        }

        const uint32_t aB  = as_b + (uint32_t)(s * A_STG_B + (mw + aRow) * AST_B + aColB);
        const uint32_t bhB = bs_b + (uint32_t)(s * B_STG_B + bRow * BST_B + bColB);

        unsigned ah[2][4];
#pragma unroll
        for (int mg = 0; mg < 2; mg++)
            ldsm4(ah[mg], aB + (uint32_t)(mg * 16 * AST_B));
#pragma unroll
        for (int g = 0; g < 4; g++) {
            unsigned bh[4];
            ldsm4t(bh, bhB + (uint32_t)((nw + g * 16) * 2));
#pragma unroll
            for (int half = 0; half < 2; half++) {
                const unsigned b0 = bh[half * 2], b1 = bh[half * 2 + 1];
                const int ng = g * 2 + half;
#pragma unroll
                for (int mg = 0; mg < 2; mg++)
                    mma_f16(acc[mg][ng], ah[mg][0], ah[mg][1], ah[mg][2], ah[mg][3], b0, b1);
            }
        }
    }

    const float qsc = QKSCALE * LOG2E;
#pragma unroll
    for (int mg = 0; mg < 2; mg++) {
        const int row0 = m0 + mw + mg * 16 + r;
        const int row1 = row0 + 8;
#pragma unroll
        for (int ng = 0; ng < 8; ng++) {
            const int col = n0 + nw + ng * 8 + 2 * c;
            const float bs0 = bias[col], bs1 = bias[col + 1];
            float v00 = acc[mg][ng][0] + bs0, v01 = acc[mg][ng][1] + bs1;
            float v10 = acc[mg][ng][2] + bs0, v11 = acc[mg][ng][3] + bs1;
            if (qkv_mode == 0) {
                *(float2*)&C[(int64_t)row0 * N + col] = make_float2(v00, v01);
                *(float2*)&C[(int64_t)row1 * N + col] = make_float2(v10, v11);
            } else {
                const int part = col / DIM;
                const int rest = col - part * DIM;
                const int head = rest >> 6;
                const int d0   = rest & 63;
                if (part == 0) {
                    *(__half2*)&g_qh[(head * NTOK + row0) * HD + d0] =
                        __floats2half2_rn(v00 * qsc, v01 * qsc);
                    *(__half2*)&g_qh[(head * NTOK + row1) * HD + d0] =
                        __floats2half2_rn(v10 * qsc, v11 * qsc);
                } else if (part == 1) {
                    *(__half2*)&g_k[(head * NTOK + row0) * HD + d0] = __floats2half2_rn(v00, v01);
                    *(__half2*)&g_k[(head * NTOK + row1) * HD + d0] = __floats2half2_rn(v10, v11);
                } else {
                    __half* vt = g_v + head * HD * NTOK;
                    vt[(d0    ) * NTOK + row0] = __float2half_rn(v00);
                    vt[(d0 + 1) * NTOK + row0] = __float2half_rn(v01);
                    vt[(d0    ) * NTOK + row1] = __float2half_rn(v10);
                    vt[(d0 + 1) * NTOK + row1] = __float2half_rn(v11);
                }
            }
        }
    }
}

// ---------------------------------------------------------------------------
// Tensor-core rel-pos (unchanged from round 13)
// ---------------------------------------------------------------------------
__global__ void __launch_bounds__(128)
relpos_tc_kernel(const __half* __restrict__ gqh,
                 const __half* __restrict__ rph,
                 const __half* __restrict__ rpw,
                 float* __restrict__ outh,
                 float* __restrict__ outw)
{
    __shared__ __align__(16) char Asm[64 * 144];
    __shared__ __align__(16) char Bsm[64 * 144];

    const int fixed = blockIdx.x;
    const int head  = blockIdx.y;
    const int mode  = blockIdx.z;
    const int t     = threadIdx.x;
    const int lane  = t & 31;
    const int w     = t >> 5;
    const int r     = lane >> 2;
    const int c     = lane & 3;

    const __half* rp = mode ? rpw : rph;
    float* out = mode ? outw : outh;
    const __half* qbase = gqh + head * NTOK * HD;

    const uint32_t as_sm = (uint32_t)__cvta_generic_to_shared(Asm);
    const uint32_t bs_sm = (uint32_t)__cvta_generic_to_shared(Bsm);

#pragma unroll
    for (int i = 0; i < 4; i++) {
        const int ch = t + i * 128;
        const int row = ch >> 3, co = (ch & 7) * 16;
        const int tok = mode ? (row * 64 + fixed) : (fixed * 64 + row);
        cp16(as_sm + (uint32_t)(row * 144 + co), (const char*)(qbase + tok * HD) + co);
        cp16(bs_sm + (uint32_t)(row * 144 + co), (const char*)(rp + (fixed - row + 63) * HD) + co);
    }
    CP_COMMIT();
    asm volatile("cp.async.wait_group 0;\n");
    __syncthreads();

    const uint32_t aB = as_sm + (uint32_t)((w * 16 + (lane & 15)) * 144 + (lane >> 4) * 16);
    const uint32_t bB = bs_sm + (uint32_t)((lane & 15) * 144 + (lane >> 4) * 16);

    unsigned qa[4][4];
#pragma unroll
    for (int kk = 0; kk < 4; kk++)
        ldsm4(qa[kk], aB + (uint32_t)(kk * 32));

    float S[8][4];
#pragma unroll
    for (int n = 0; n < 8; n++)
#pragma unroll
        for (int j = 0; j < 4; j++) S[n][j] = 0.f;

#pragma unroll
    for (int kk = 0; kk < 4; kk++) {
#pragma unroll
        for (int g = 0; g < 4; g++) {
            unsigned bb[4];
            ldsm4(bb, bB + (uint32_t)(g * 16 * 144 + kk * 32));
            mma_f16(S[g*2],   qa[kk][0], qa[kk][1], qa[kk][2], qa[kk][3], bb[0], bb[2]);
            mma_f16(S[g*2+1], qa[kk][0], qa[kk][1], qa[kk][2], qa[kk][3], bb[1], bb[3]);
        }
    }

    const int arow0 = w * 16 + r, arow1 = arow0 + 8;
    const int tok0 = mode ? (arow0 * 64 + fixed) : (fixed * 64 + arow0);
    const int tok1 = mode ? (arow1 * 64 + fixed) : (fixed * 64 + arow1);
    float* o0 = out + (head * NTOK + tok0) * HD;
    float* o1 = out + (head * NTOK + tok1) * HD;
#pragma unroll
    for (int n = 0; n < 8; n++) {
        const int col = n * 8 + 2 * c;
        *(float2*)&o0[col] = make_float2(S[n][0] * 8.f, S[n][1] * 8.f);
        *(float2*)&o1[col] = make_float2(S[n][2] * 8.f, S[n][3] * 8.f);
    }
}

// ---------------------------------------------------------------------------
// Flash attention v13 (EXACT round-13 best: 128 thr, 4 warps x 32 Q-rows,
// 3-stage cp.async, f16x2 softmax, l via ones-MMA, split 22/21/21)
// ---------------------------------------------------------------------------
#define STRH      72
#define ROW_B     144
#define KV_TILE_B (64 * ROW_B)               // 9216 B per tile
#define PQ_B      (128 * ROW_B)              // 18432 B
#define FLASH_SMEM_B (6 * KV_TILE_B + PQ_B)  // 73728 B
#define ONESH2 0x3C003C00u

__global__ void __launch_bounds__(128, 2)
flash_v13_kernel(const __half* __restrict__ gqh,
                 const __half* __restrict__ gk,
                 const __half* __restrict__ gvt,
                 const float* __restrict__ grh,
                 const float* __restrict__ grw,
                 float* __restrict__ po,
                 float* __restrict__ pl)
{
    extern __shared__ char smc[];
    char*   Ksc = smc;                        // 3 stages x 64 x 144B
    char*   Vsc = smc + 3 * KV_TILE_B;        // 3 stages x 64 x 144B
    __half* PQh = (__half*)(smc + 6 * KV_TILE_B);   // 128 x 72 halves (Q -> P)

    const int qt   = blockIdx.x;
    const int head = blockIdx.y;
    const int z    = blockIdx.z;
    const int ktb  = (z == 0) ? 0 : (22 + 21 * (z - 1));   // 0, 22, 43
    const int nit  = (z == 0) ? 22 : 21;
    const int t    = threadIdx.x;
    const int lane = t & 31;
    const int w    = t >> 5;
    const int r    = lane >> 2;
    const int c    = lane & 3;
    const int mbase = w * 32;

    const __half* qbh  = gqh + (head * NTOK + qt * 128) * HD;
    const __half* kb0  = gk  + head * NTOK * HD;
    const char*   vtb0 = (const char*)(gvt + head * HD * NTOK);
    const float*  rhb  = grh + (head * NTOK + qt * 128 + mbase) * HD;
    const float*  rwb  = grw + (head * NTOK + qt * 128 + mbase) * HD;

    const uint32_t ks_sm = (uint32_t)__cvta_generic_to_shared(Ksc);
    const uint32_t vs_sm = (uint32_t)__cvta_generic_to_shared(Vsc);
    const uint32_t pq_sm = (uint32_t)__cvta_generic_to_shared(PQh);

    #define LOAD_KV(st, kt) do {                                              \
        const char* kb_ = (const char*)(kb0 + (kt) * 64 * HD);                \
        const uint32_t kd_ = ks_sm + (uint32_t)((st) * KV_TILE_B);            \
        const uint32_t vd_ = vs_sm + (uint32_t)((st) * KV_TILE_B);            \
        _Pragma("unroll")                                                     \
        for (int i_ = 0; i_ < 4; i_++) {                                      \
            const int ch_ = t + i_ * 128;                                     \
            const int row_ = ch_ >> 3, co_ = (ch_ & 7) * 16;                  \
            cp16(kd_ + row_ * ROW_B + co_, kb_ + row_ * 128 + co_);           \
            cp16(vd_ + row_ * ROW_B + co_,                                    \
                 vtb0 + row_ * (NTOK * 2) + (kt) * 128 + co_);                \
        }                                                                     \
    } while (0)

    // prologue: prefetch K/V tiles ktb, ktb+1 and Q (all cp.async)
    LOAD_KV(0, ktb);     CP_COMMIT();
    LOAD_KV(1, ktb + 1); CP_COMMIT();
#pragma unroll
    for (int i_ = 0; i_ < 8; i_++) {
        const int ch_ = t + i_ * 128;
        const int row_ = ch_ >> 3, co_ = (ch_ & 7) * 16;
        cp16(pq_sm + (uint32_t)(row_ * ROW_B + co_), (const char*)qbh + row_ * 128 + co_);
    }
    CP_COMMIT();
    asm volatile("cp.async.wait_group 0;\n");
    __syncthreads();

    // Q fragments (persist)
    const uint32_t aBase = pq_sm + (uint32_t)((mbase + (lane & 15)) * ROW_B
                                              + (lane >> 4) * 16);
    unsigned qa[2][4][4];
#pragma unroll
    for (int mb = 0; mb < 2; mb++)
#pragma unroll
        for (int kk = 0; kk < 4; kk++)
            ldsm4(qa[mb][kk], aBase + (uint32_t)(mb * 16 * ROW_B + kk * 32));
    __syncwarp();

    // rw bias (log2 domain), packed fp16x2: [mb][rowgroup][n]
    __half2 rwh[2][2][8];
#pragma unroll
    for (int mb = 0; mb < 2; mb++)
#pragma unroll
        for (int rg = 0; rg < 2; rg++)
#pragma unroll
            for (int n = 0; n < 8; n++) {
                float2 v = *(const float2*)&rwb[(mb * 16 + rg * 8 + r) * HD + n * 8 + 2 * c];
                rwh[mb][rg][n] = __floats2half2_rn(v.x, v.y);
            }

    float O[2][8][4];
#pragma unroll
    for (int mb = 0; mb < 2; mb++)
#pragma unroll
        for (int n = 0; n < 8; n++)
#pragma unroll
            for (int j = 0; j < 4; j++) O[mb][n][j] = 0.f;
    float lacc[2][4];
#pragma unroll
    for (int mb = 0; mb < 2; mb++)
#pragma unroll
        for (int j = 0; j < 4; j++) lacc[mb][j] = 0.f;

    for (int it = 0; it < nit; it++) {
        const int kt = ktb + it;
        const int s  = it % 3;

        asm volatile("cp.async.wait_group 1;\n");
        __syncthreads();   // tile kt ready; stage (it+2)%3 free

        if (it + 2 < nit) LOAD_KV((it + 2) % 3, kt + 2);
        CP_COMMIT();

        float rh[2][2];
#pragma unroll
        for (int mb = 0; mb < 2; mb++) {
            rh[mb][0] = __ldg(&rhb[(mb * 16 + r) * HD + kt])     - M0SHIFT;
            rh[mb][1] = __ldg(&rhb[(mb * 16 + 8 + r) * HD + kt]) - M0SHIFT;
        }

        const uint32_t kS = ks_sm + (uint32_t)(s * KV_TILE_B)
                              + (lane & 15) * ROW_B + (lane >> 4) * 16;
        const uint32_t vS = vs_sm + (uint32_t)(s * KV_TILE_B)
                              + (lane & 15) * ROW_B + (lane >> 4) * 16;

        // ---- S = Q K^T over full 64 keys ----
        float S[2][8][4];
#pragma unroll
        for (int mb = 0; mb < 2; mb++)
#pragma unroll
            for (int n = 0; n < 8; n++)
#pragma unroll
                for (int j = 0; j < 4; j++) S[mb][n][j] = 0.f;

#pragma unroll
        for (int kk = 0; kk < 4; kk++) {
#pragma unroll
            for (int g = 0; g < 4; g++) {
                unsigned bb[4];
                ldsm4(bb, kS + (uint32_t)(g * 16 * ROW_B + kk * 32));
                mma_f16(S[0][g*2],   qa[0][kk][0], qa[0][kk][1], qa[0][kk][2], qa[0][kk][3], bb[0], bb[2]);
                mma_f16(S[0][g*2+1], qa[0][kk][0], qa[0][kk][1], qa[0][kk][2], qa[0][kk][3], bb[1], bb[3]);
                mma_f16(S[1][g*2],   qa[1][kk][0], qa[1][kk][1], qa[1][kk][2], qa[1][kk][3], bb[0], bb[2]);
                mma_f16(S[1][g*2+1], qa[1][kk][0], qa[1][kk][1], qa[1][kk][2], qa[1][kk][3], bb[1], bb[3]);
            }
        }

        // ---- fixed-shift softmax: p = 2^(S + rh' + rw'), f16x2 exp ----
#pragma unroll
        for (int mb = 0; mb < 2; mb++) {
            const float a0 = rh[mb][0];
            const float a1 = rh[mb][1];
            __half* prow0 = PQh + (mbase + mb * 16 + r) * STRH + 2 * c;
            __half* prow1 = prow0 + 8 * STRH;
#pragma unroll
            for (int n = 0; n < 8; n++) {
                __half2 h01 = __floats2half2_rn(S[mb][n][0] + a0, S[mb][n][1] + a0);
                __half2 h23 = __floats2half2_rn(S[mb][n][2] + a1, S[mb][n][3] + a1);
                __half2 p01 = ex2h2(__hadd2(h01, rwh[mb][0][n]));
                __half2 p23 = ex2h2(__hadd2(h23, rwh[mb][1][n]));
                *(__half2*)(prow0 + n * 8) = p01;
                *(__half2*)(prow1 + n * 8) = p23;
            }
        }
        __syncwarp();   // P rows warp-private

        // ---- O += P V; l += P * ones ----
#pragma unroll
        for (int kk2 = 0; kk2 < 4; kk2++) {
            unsigned pa[2][4];
            ldsm4(pa[0], aBase + (uint32_t)(kk2 * 32));
            ldsm4(pa[1], aBase + (uint32_t)(16 * ROW_B + kk2 * 32));
            mma_f16(lacc[0], pa[0][0], pa[0][1], pa[0][2], pa[0][3], ONESH2, ONESH2);
            mma_f16(lacc[1], pa[1][0], pa[1][1], pa[1][2], pa[1][3], ONESH2, ONESH2);
#pragma unroll
            for (int p = 0; p < 4; p++) {
                unsigned vv[4];
                ldsm4(vv, vS + (uint32_t)(p * 16 * ROW_B + kk2 * 32));
                mma_f16(O[0][p*2],   pa[0][0], pa[0][1], pa[0][2], pa[0][3], vv[0], vv[2]);
                mma_f16(O[0][p*2+1], pa[0][0], pa[0][1], pa[0][2], pa[0][3], vv[1], vv[3]);
                mma_f16(O[1][p*2],   pa[1][0], pa[1][1], pa[1][2], pa[1][3], vv[0], vv[2]);
                mma_f16(O[1][p*2+1], pa[1][0], pa[1][1], pa[1][2], pa[1][3], vv[1], vv[3]);
            }
        }
        __syncwarp();   // P reads done before next iter's stores
    }

    // ---- epilogue ----
    const int pz = z * NH * NTOK + head * NTOK;
#pragma unroll
    for (int mb = 0; mb < 2; mb++) {
        const int row0 = qt * 128 + mbase + mb * 16 + r;
        const int row1 = row0 + 8;
        if (c == 0) {
            pl[pz + row0] = lacc[mb][0];
            pl[pz + row1] = lacc[mb][2];
        }
#pragma unroll
        for (int n = 0; n < 8; n++) {
            const int col = n * 8 + 2 * c;
            *(float2*)&po[(pz + row0) * HD + col] = make_float2(O[mb][n][0], O[mb][n][1]);
            *(float2*)&po[(pz + row1) * HD + col] = make_float2(O[mb][n][2], O[mb][n][3]);
        }
    }
}

// ---------------------------------------------------------------------------
// merge the three KV-third partials -> g_aoh (fp16, feeds proj GEMM)
// ---------------------------------------------------------------------------
__global__ void merge_kernel(const float* __restrict__ po,
                             const float* __restrict__ pl,
                             __half* __restrict__ aoh)
{
    const int gid = blockIdx.x * 256 + threadIdx.x;
    const int dp  = (gid & 7) * 8;
    const int hr  = gid >> 3;
    const int head = hr >> 12, row = hr & 4095;
    const int S = NH * NTOK;

    const float inv = 1.0f / (pl[hr] + pl[S + hr] + pl[2 * S + hr]);

    const float* o0 = po + (size_t)hr * HD + dp;
    const float* o1 = po + (size_t)(S + hr) * HD + dp;
    const float* o2 = po + (size_t)(2 * S + hr) * HD + dp;
    __half* dst = aoh + row * DIM + head * HD + dp;

    uint4 outw;
    unsigned* ow = (unsigned*)&outw;
#pragma unroll
    for (int j = 0; j < 8; j += 2) {
        float x = (o0[j]     + o1[j]     + o2[j])     * inv;
        float y = (o0[j + 1] + o1[j + 1] + o2[j + 1]) * inv;
        __half2 h = __floats2half2_rn(x, y);
        ow[j >> 1] = *(unsigned*)&h;
    }
    *(uint4*)dst = outw;
}

// ---------------------------------------------------------------------------
extern "C" void kernel_launch(void* const* d_in, const int* in_sizes, int n_in,
                              void* d_out, int out_size)
{
    const float* x        = (const float*)d_in[0];
    const float* w_qkv    = (const float*)d_in[1];
    const float* b_qkv    = (const float*)d_in[2];
    const float* w_proj   = (const float*)d_in[3];
    const float* b_proj   = (const float*)d_in[4];
    const float* rel_h    = (const float*)d_in[5];
    const float* rel_w    = (const float*)d_in[6];
    float* out = (float*)d_out;

    float *grh, *grw, *gpo, *gpl;
    __half *gqh, *gk, *gv, *gxh, *gwqh, *gwph, *gaoh, *grph, *grpw;
    cudaGetSymbolAddress((void**)&gqh,  g_qh);
    cudaGetSymbolAddress((void**)&gk,   g_k);
    cudaGetSymbolAddress((void**)&gv,   g_v);
    cudaGetSymbolAddress((void**)&grh,  g_relh);
    cudaGetSymbolAddress((void**)&grw,  g_relw);
    cudaGetSymbolAddress((void**)&gpo,  g_po);
    cudaGetSymbolAddress((void**)&gpl,  g_pl);
    cudaGetSymbolAddress((void**)&gxh,  g_xh);
    cudaGetSymbolAddress((void**)&gwqh, g_wqh);
    cudaGetSymbolAddress((void**)&gwph, g_wph);
    cudaGetSymbolAddress((void**)&gaoh, g_aoh);
    cudaGetSymbolAddress((void**)&grph, g_rph);
    cudaGetSymbolAddress((void**)&grpw, g_rpw);

    // 0) fused conversion of all operands to fp16
    const int NCONV = NX4 + NWQ4 + NWP4 + 2 * NRP4;
    conv_all_kernel<<<(NCONV + 255) / 256, 256>>>(x, w_qkv, w_proj, rel_h, rel_w);

    cudaFuncSetAttribute(gemm_f16_kernel,
                         cudaFuncAttributeMaxDynamicSharedMemorySize, GEMM_SMEM_B);

    // 1) QKV GEMM (fp16 x1, 4-stage cp.async)
    gemm_f16_kernel<<<dim3(3 * DIM / 128, NTOK / 128), 256, GEMM_SMEM_B>>>(
        gxh, gwqh, b_qkv, nullptr, 3 * DIM, DIM, 1);

    // 2) rel_h / rel_w via tensor cores
    relpos_tc_kernel<<<dim3(GRID_HW, NH, 2), 128>>>(gqh, grph, grpw, grh, grw);

    // 3) flash attention v13 (exact round-13 best, split-KV x3)
    cudaFuncSetAttribute(flash_v13_kernel,
                         cudaFuncAttributeMaxDynamicSharedMemorySize, FLASH_SMEM_B);
    flash_v13_kernel<<<dim3(NTOK / 128, NH, NSPLIT), 128, FLASH_SMEM_B>>>(
        gqh, gk, gv, grh, grw, gpo, gpl);

    // 4) merge partials -> fp16 ao
    merge_kernel<<<NH * NTOK * 8 / 256, 256>>>(gpo, gpl, gaoh);

    // 5) output projection (fp16 x1, 4-stage cp.async)
    gemm_f16_kernel<<<dim3(DIM / 128, NTOK / 128), 256, GEMM_SMEM_B>>>(
        gaoh, gwph, b_proj, out, DIM, DIM, 0);
}